// round 4
// baseline (speedup 1.0000x reference)
#include <cuda_runtime.h>
#include <stdint.h>

#define CAP   6144     // stage-1 candidates (raw x, x > sample_max - 2)
#define CAP2  2048     // stage-2 candidates (Y > -1, true support superset)
#define MAX_ROWS 16384
#define SAMPLE 4096

__device__ float g_row_loss[MAX_ROWS];

__device__ __forceinline__ float warpMax(float v) {
    #pragma unroll
    for (int o = 16; o; o >>= 1) v = fmaxf(v, __shfl_xor_sync(0xffffffffu, v, o));
    return v;
}
__device__ __forceinline__ float warpSum(float v) {
    #pragma unroll
    for (int o = 16; o; o >>= 1) v += __shfl_xor_sync(0xffffffffu, v, o);
    return v;
}

__global__ __launch_bounds__(512, 4)
void entmax15_loss_kernel(const float* __restrict__ input,
                          const void* __restrict__ target,
                          int n, int d) {
    __shared__ float cand[CAP];     // raw x values
    __shared__ float candY[CAP2];   // Y = x/2 - M, filtered to Y > -1
    __shared__ float shA[16], shB[16], shC[16];
    __shared__ float s_red0, s_red1;
    __shared__ int   s_count, s_count2, s_tg32;
    __shared__ float s_tau, s_xt;

    const int tid  = threadIdx.x;
    const int lane = tid & 31;
    const int wid  = tid >> 5;
    const int bd   = blockDim.x;
    const int nw   = bd >> 5;

    const float* in_row = input + (size_t)blockIdx.x * (size_t)d;
    const bool al = ((((uintptr_t)in_row) & 15) == 0) && ((d & 3) == 0);

    if (tid == 0) { s_count = 0; s_count2 = 0; }

    // ---- dtype probe (warp 0): int32 target read as int64 is out of [0,d) ----
    if (wid == 0) {
        int lim = n >> 1; if (lim > 32) lim = 32;
        bool bad = false;
        if (lane < lim) {
            long long v = ((const long long*)target)[lane];
            bad = (v < 0 || v >= (long long)d);
        }
        unsigned mk = __ballot_sync(0xffffffffu, bad);
        if (lane == 0) s_tg32 = (mk != 0);
    }

    // ---- Sample max over first SAMPLE elements (tiny, L2-resident) ----
    const int slen = (d < SAMPLE) ? d : SAMPLE;
    float smax = -INFINITY;
    if (al) {
        const float4* in4 = (const float4*)in_row;
        const int s4 = slen >> 2;
        for (int i = tid; i < s4; i += bd) {
            float4 v = in4[i];
            smax = fmaxf(fmaxf(v.x, v.y), fmaxf(fmaxf(v.z, v.w), smax));
        }
    } else {
        for (int i = tid; i < slen; i += bd) smax = fmaxf(smax, in_row[i]);
    }
    smax = warpMax(smax);
    if (lane == 0) shA[wid] = smax;
    __syncthreads();
    if (tid < 32) {
        float m = (tid < nw) ? shA[tid] : -INFINITY;
        m = warpMax(m);
        if (tid == 0) s_red0 = m;
    }
    __syncthreads();
    const float thr = s_red0 - 2.0f;   // collect x > thr  (superset of Y > -1)

    if (tid == 0) {
        long long tg = s_tg32 ? (long long)(((const int*)target)[blockIdx.x])
                              : ((const long long*)target)[blockIdx.x];
        if (tg < 0) tg = 0;
        if (tg >= d) tg = d - 1;
        s_xt = in_row[tg];
    }

    // ---- SINGLE full-row pass: true max + candidate collection ----
    float vmax = -INFINITY;
    if (al) {
        const float4* in4 = (const float4*)in_row;
        const int d4 = d >> 2;
        #pragma unroll 4
        for (int i = tid; i < d4; i += bd) {
            float4 v = in4[i];
            vmax = fmaxf(fmaxf(v.x, v.y), fmaxf(fmaxf(v.z, v.w), vmax));
            if (v.x > thr) { int id = atomicAdd(&s_count, 1); if (id < CAP) cand[id] = v.x; }
            if (v.y > thr) { int id = atomicAdd(&s_count, 1); if (id < CAP) cand[id] = v.y; }
            if (v.z > thr) { int id = atomicAdd(&s_count, 1); if (id < CAP) cand[id] = v.z; }
            if (v.w > thr) { int id = atomicAdd(&s_count, 1); if (id < CAP) cand[id] = v.w; }
        }
    } else {
        for (int i = tid; i < d; i += bd) {
            float x = in_row[i];
            vmax = fmaxf(vmax, x);
            if (x > thr) { int id = atomicAdd(&s_count, 1); if (id < CAP) cand[id] = x; }
        }
    }
    vmax = warpMax(vmax);
    if (lane == 0) shA[wid] = vmax;
    __syncthreads();
    if (tid < 32) {
        float m = (tid < nw) ? shA[tid] : -INFINITY;
        m = warpMax(m);
        if (tid == 0) s_red0 = m;
    }
    __syncthreads();
    const float M = 0.5f * s_red0;          // max of X = input/2
    const int  count = s_count;
    const bool fit = (count <= CAP);        // block-uniform

    // ---- Stage-2 compaction: keep only Y = x/2 - M > -1 ----
    if (fit) {
        for (int i = tid; i < count; i += bd) {
            float y = fmaf(0.5f, cand[i], -M);
            if (y > -1.0f) { int id = atomicAdd(&s_count2, 1); if (id < CAP2) candY[id] = y; }
        }
    }
    __syncthreads();
    const int  count2 = s_count2;
    const bool fit2 = fit && (count2 <= CAP2);

    // ---- Newton on f(tau) = sum max(Y - tau, 0)^2 = 1, root in [-1, 0) ----
    // f convex decreasing => monotone convergence from tau = -1.
    // Spurious candidates (Y <= -1) never contribute since tau >= -1.
    float tau;
    if (fit) {
        const float* buf = fit2 ? candY : cand;
        const int    len = fit2 ? count2 : count;
        const bool   isY = fit2;
        if (wid == 0) {
            float tl = -1.0f;
            #pragma unroll 1
            for (int it = 0; it < 20; ++it) {
                float s1 = 0.f, s2 = 0.f;
                for (int i = lane; i < len; i += 32) {
                    float y = isY ? buf[i] : fmaf(0.5f, buf[i], -M);
                    float t = y - tl;
                    if (t > 0.f) { s1 += t; s2 = fmaf(t, t, s2); }
                }
                s1 = warpSum(s1); s2 = warpSum(s2);
                float corr = (s2 - 1.0f) / (2.0f * fmaxf(s1, 1e-30f));
                tl += corr;
                if (fabsf(corr) < 1e-8f) break;
            }
            if (lane == 0) s_tau = tl;
        }
        __syncthreads();
        tau = s_tau;
    } else {
        // Rare fallback: block-wide Newton over the full row (L2 reads).
        tau = -1.0f;
        for (int it = 0; it < 24; ++it) {
            float s1 = 0.f, s2 = 0.f;
            for (int i = tid; i < d; i += bd) {
                float t = fmaf(0.5f, in_row[i], -M) - tau;
                if (t > 0.f) { s1 += t; s2 = fmaf(t, t, s2); }
            }
            s1 = warpSum(s1); s2 = warpSum(s2);
            if (lane == 0) { shA[wid] = s1; shB[wid] = s2; }
            __syncthreads();
            if (tid < 32) {
                float a = (tid < nw) ? shA[tid] : 0.f;
                float b = (tid < nw) ? shB[tid] : 0.f;
                a = warpSum(a); b = warpSum(b);
                if (tid == 0) { s_red0 = a; s_red1 = b; }
            }
            __syncthreads();
            tau += (s_red1 - 1.0f) / (2.0f * fmaxf(s_red0, 1e-30f));
            __syncthreads();
        }
    }

    // ---- Epilogue: t3 = sum t^3, py = sum t^2*Y, p2 = sum t^2 ----
    // loss = (1 - t3)*4/3 + 2*py + 2*M*p2 - x[target]
    float t3 = 0.f, py = 0.f, p2 = 0.f;
    if (fit) {
        const float* buf = fit2 ? candY : cand;
        const int    len = fit2 ? count2 : count;
        const bool   isY = fit2;
        for (int i = tid; i < len; i += bd) {
            float y = isY ? buf[i] : fmaf(0.5f, buf[i], -M);
            float t = y - tau;
            if (t > 0.f) { float p = t * t; t3 = fmaf(p, t, t3); py = fmaf(p, y, py); p2 += p; }
        }
    } else {
        for (int i = tid; i < d; i += bd) {
            float y = fmaf(0.5f, in_row[i], -M);
            float t = y - tau;
            if (t > 0.f) { float p = t * t; t3 = fmaf(p, t, t3); py = fmaf(p, y, py); p2 += p; }
        }
    }
    t3 = warpSum(t3); py = warpSum(py); p2 = warpSum(p2);
    if (lane == 0) { shA[wid] = t3; shB[wid] = py; shC[wid] = p2; }
    __syncthreads();
    if (tid < 32) {
        float a = (tid < nw) ? shA[tid] : 0.f;
        float b = (tid < nw) ? shB[tid] : 0.f;
        float c = (tid < nw) ? shC[tid] : 0.f;
        a = warpSum(a); b = warpSum(b); c = warpSum(c);
        if (tid == 0) {
            float omega = (1.0f - a) * (4.0f / 3.0f);
            g_row_loss[blockIdx.x] = omega + 2.0f * b + 2.0f * M * c - s_xt;
        }
    }
}

__global__ void reduce_mean_kernel(int n, float* __restrict__ out) {
    __shared__ float sh[32];
    float a = 0.f;
    for (int i = threadIdx.x; i < n; i += blockDim.x) a += g_row_loss[i];
    a = warpSum(a);
    if ((threadIdx.x & 31) == 0) sh[threadIdx.x >> 5] = a;
    __syncthreads();
    if (threadIdx.x < 32) {
        int nw = (blockDim.x + 31) >> 5;
        float v = (threadIdx.x < nw) ? sh[threadIdx.x] : 0.f;
        v = warpSum(v);
        if (threadIdx.x == 0) *out = v / (float)n;
    }
}

extern "C" void kernel_launch(void* const* d_in, const int* in_sizes, int n_in,
                              void* d_out, int out_size) {
    const int i_in = (in_sizes[0] >= in_sizes[1]) ? 0 : 1;
    const int i_tg = 1 - i_in;
    const float* input  = (const float*)d_in[i_in];
    const void*  target = d_in[i_tg];
    const int n = in_sizes[i_tg];
    const int d = in_sizes[i_in] / n;

    entmax15_loss_kernel<<<n, 512>>>(input, target, n, d);
    reduce_mean_kernel<<<1, 1024>>>(n, (float*)d_out);
}